// round 3
// baseline (speedup 1.0000x reference)
#include <cuda_runtime.h>

#define BB 64
#define SS 48
#define EE 512
#define HH 512
#define GG 2048
#define NCTA 128

// ---------------- persistent device scratch (no allocs allowed) ----------------
__device__ float g_gih0[2][SS][BB][GG];   // LN(x @ W_ih0^T), both dirs  (~50MB)
__device__ float g_u[2][BB][GG];          // per-step h @ W_hh^T (raw)
__device__ float g_g1[2][BB][GG];         // layer-1 LN(xc @ W_ih1^T)
__device__ float g_h[2][BB][HH];
__device__ float g_c[2][BB][HH];
__device__ float g_psum[2][64][BB];       // [dir][g-chunk][b] row partial sums
__device__ float g_psq[2][64][BB];
__device__ unsigned g_barcnt = 0;
__device__ unsigned g_excnt = 0;

__device__ __forceinline__ float sigmoidf_(float x) { return 1.0f / (1.0f + expf(-x)); }

// ---------------- grid-wide barrier (all NCTA CTAs co-resident) ----------------
__device__ __forceinline__ void grid_sync(unsigned &target) {
    __syncthreads();
    if (threadIdx.x == 0) {
        __threadfence();                       // publish my CTA's stores gpu-wide
        atomicAdd(&g_barcnt, 1u);
        target += NCTA;
        while (atomicAdd(&g_barcnt, 0u) < target) { __nanosleep(64); }
    }
    __syncthreads();
    __threadfence();                           // reader-side: invalidate stale L1 (CCTL.IVALL)
}

// ---------------- block-wide mean/rstd over (sum, sumsq) contributions ---------
__device__ __forceinline__ void block_stats(float s, float q, float invN,
                                            float &mu, float &rs) {
    __shared__ float redS[8], redQ[8], bc[2];
    int t = threadIdx.x;
    __syncthreads();   // protect shared reuse across calls
#pragma unroll
    for (int o = 16; o > 0; o >>= 1) {
        s += __shfl_xor_sync(0xFFFFFFFFu, s, o);
        q += __shfl_xor_sync(0xFFFFFFFFu, q, o);
    }
    if ((t & 31) == 0) { redS[t >> 5] = s; redQ[t >> 5] = q; }
    __syncthreads();
    if (t == 0) {
        float S = 0.f, Q = 0.f;
#pragma unroll
        for (int i = 0; i < 8; i++) { S += redS[i]; Q += redQ[i]; }
        float m = S * invN;
        bc[0] = m;
        bc[1] = rsqrtf(Q * invN - m * m + 1e-5f);
    }
    __syncthreads();
    mu = bc[0]; rs = bc[1];
}

// ================= Phase A: raw x @ W_ih0^T for all (d, s) =====================
// grid = 2 * 48 * 32 = 3072 CTAs; each CTA: 64 b x 64 g tile, K = 512.
__global__ void __launch_bounds__(256) phaseA_gemm(const float* __restrict__ x,
                                                   const float* __restrict__ w_ih0) {
    int r = blockIdx.x;
    int d = r / (SS * 32);
    int rem = r % (SS * 32);
    int s = rem / 32;
    int gt = rem % 32;
    int g0 = gt * 64;

    __shared__ float xs[64][64];              // 16KB  x[b][k] tile
    int t = threadIdx.x;
    int gl = t & 63;
    int g = g0 + gl;
    int bgrp = t >> 6;                         // 0..3 -> 16 b's each
    const float* Wr = w_ih0 + ((size_t)d * GG + g) * EE;

    float acc[16];
#pragma unroll
    for (int j = 0; j < 16; j++) acc[j] = 0.f;

    for (int kt = 0; kt < EE / 64; kt++) {
        int k0 = kt * 64;
#pragma unroll
        for (int i = 0; i < 4; i++) {          // 1024 float4 loads total
            int fi = t + 256 * i;
            int b = fi >> 4;
            int kq = fi & 15;
            *(float4*)&xs[b][kq * 4] =
                *(const float4*)(x + ((size_t)b * SS + s) * EE + k0 + kq * 4);
        }
        __syncthreads();
#pragma unroll 8
        for (int k = 0; k < 64; k += 4) {
            float4 wv = *(const float4*)(Wr + k0 + k);
#pragma unroll
            for (int j = 0; j < 16; j++) {
                float4 hv = *(const float4*)&xs[bgrp * 16 + j][k];
                acc[j] += wv.x * hv.x + wv.y * hv.y + wv.z * hv.z + wv.w * hv.w;
            }
        }
        __syncthreads();
    }
#pragma unroll
    for (int j = 0; j < 16; j++)
        g_gih0[d][s][bgrp * 16 + j][g] = acc[j];
}

// ================= Phase A LN (in place, with ln_ih0 params) ===================
// grid = 2 * 48 * 64 = 6144 rows of 2048.
__global__ void __launch_bounds__(256) phaseA_ln(const float* __restrict__ gam,
                                                 const float* __restrict__ bet) {
    int r = blockIdx.x;
    int d = r / (SS * BB);
    int rem = r % (SS * BB);
    int s = rem / BB;
    int b = rem % BB;
    float* row = &g_gih0[d][s][b][0];
    int t = threadIdx.x;
    float v[8];
    float sum = 0.f, sq = 0.f;
#pragma unroll
    for (int i = 0; i < 8; i++) {
        v[i] = row[t + 256 * i];
        sum += v[i]; sq += v[i] * v[i];
    }
    float mu, rs;
    block_stats(sum, sq, 1.0f / GG, mu, rs);
    const float* gm = gam + d * GG;
    const float* bt = bet + d * GG;
#pragma unroll
    for (int i = 0; i < 8; i++) {
        int g = t + 256 * i;
        row[g] = (v[i] - mu) * rs * gm[g] + bt[g];
    }
}

// ================= scan kernel building blocks ================================
// GEMM tile: this CTA computes u[d][b][chunk*32 .. +32) for all 64 b, K in {512,1024}.
__device__ void step_gemm(int d, int chunk, const float* __restrict__ Wd, int K,
                          const float* __restrict__ src0, const float* __restrict__ src1) {
    __shared__ float hs[BB][128];             // 32KB
    int t = threadIdx.x;
    int gl = t & 31;
    int w = t >> 5;
    int g = chunk * 32 + gl;
    const float* Wr = Wd + (size_t)g * K;
    float acc[8];
#pragma unroll
    for (int j = 0; j < 8; j++) acc[j] = 0.f;

    int ntile = K >> 7;
    for (int kt = 0; kt < ntile; kt++) {
        int k0 = kt << 7;
        const float* src = (k0 < HH) ? (src0 + k0) : (src1 + (k0 - HH));
#pragma unroll
        for (int i = 0; i < 8; i++) {         // 2048 float4 loads
            int fi = t + 256 * i;
            int b = fi >> 5;
            int kq = fi & 31;
            *(float4*)&hs[b][kq * 4] = *(const float4*)(src + (size_t)b * HH + kq * 4);
        }
        __syncthreads();
#pragma unroll 8
        for (int k = 0; k < 128; k += 4) {
            float4 wv = *(const float4*)(Wr + k0 + k);
#pragma unroll
            for (int j = 0; j < 8; j++) {
                float4 hv = *(const float4*)&hs[w * 8 + j][k];
                acc[j] += wv.x * hv.x + wv.y * hv.y + wv.z * hv.z + wv.w * hv.w;
            }
        }
        __syncthreads();
    }
    // deterministic per-(chunk,b) partials (lanes of warp w = 32 g's of b = w*8+j)
#pragma unroll
    for (int j = 0; j < 8; j++) {
        int b = w * 8 + j;
        float s = acc[j], q = acc[j] * acc[j];
#pragma unroll
        for (int o = 16; o > 0; o >>= 1) {
            s += __shfl_xor_sync(0xFFFFFFFFu, s, o);
            q += __shfl_xor_sync(0xFFFFFFFFu, q, o);
        }
        if (gl == 0) { g_psum[d][chunk][b] = s; g_psq[d][chunk][b] = q; }
        g_u[d][b][g] = acc[j];
    }
}

// pointwise: this CTA owns row (d, b). LN(u) + gates + c update + LN(c) + h.
__device__ void step_point(int d, int b, const float* __restrict__ gih,
                           const float* __restrict__ hhg, const float* __restrict__ hhb,
                           const float* __restrict__ hog, const float* __restrict__ hob,
                           float* __restrict__ outrow) {
    int t = threadIdx.x;
    float s = (t < 64) ? g_psum[d][t][b] : 0.f;
    float q = (t < 64) ? g_psq[d][t][b] : 0.f;
    float mu, rs;
    block_stats(s, q, 1.0f / GG, mu, rs);

    const float* urow = &g_u[d][b][0];
    float cn[2], og[2];
    float cs = 0.f, cq = 0.f;
#pragma unroll
    for (int i = 0; i < 2; i++) {
        int j = t + 256 * i;
        float vi = gih[j]          + (urow[j]          - mu) * rs * hhg[j]          + hhb[j];
        float vf = gih[HH + j]     + (urow[HH + j]     - mu) * rs * hhg[HH + j]     + hhb[HH + j];
        float vo = gih[2 * HH + j] + (urow[2 * HH + j] - mu) * rs * hhg[2 * HH + j] + hhb[2 * HH + j];
        float vg = gih[3 * HH + j] + (urow[3 * HH + j] - mu) * rs * hhg[3 * HH + j] + hhb[3 * HH + j];
        float ig = sigmoidf_(vi);
        float fg = sigmoidf_(vf);
        og[i] = sigmoidf_(vo);
        float gg = tanhf(vg);
        float c = fg * g_c[d][b][j] + ig * gg;
        cn[i] = c;
        cs += c; cq += c * c;
    }
    float muc, rsc;
    block_stats(cs, cq, 1.0f / HH, muc, rsc);
#pragma unroll
    for (int i = 0; i < 2; i++) {
        int j = t + 256 * i;
        float hval = og[i] * tanhf((cn[i] - muc) * rsc * hog[j] + hob[j]);
        g_c[d][b][j] = cn[i];
        g_h[d][b][j] = hval;
        if (outrow) outrow[j] = hval;
    }
}

// finalize layer-1 input LN (g1) and zero states for layer 1
__device__ void g1_finalize(int d, int b, const float* __restrict__ ihg,
                            const float* __restrict__ ihb) {
    int t = threadIdx.x;
    float s = (t < 64) ? g_psum[d][t][b] : 0.f;
    float q = (t < 64) ? g_psq[d][t][b] : 0.f;
    float mu, rs;
    block_stats(s, q, 1.0f / GG, mu, rs);
#pragma unroll
    for (int i = 0; i < 8; i++) {
        int g = t + 256 * i;
        g_g1[d][b][g] = (g_u[d][b][g] - mu) * rs * ihg[g] + ihb[g];
    }
#pragma unroll
    for (int i = 0; i < 2; i++) {
        int j = t + 256 * i;
        g_h[d][b][j] = 0.f;
        g_c[d][b][j] = 0.f;
    }
}

// ================= persistent recurrent kernel ================================
__global__ void __launch_bounds__(256) scan_kernel(
    const float* __restrict__ w_hh0,
    const float* __restrict__ ln_hh0_g, const float* __restrict__ ln_hh0_b,
    const float* __restrict__ ln_ho0_g, const float* __restrict__ ln_ho0_b,
    const float* __restrict__ w_ih1, const float* __restrict__ w_hh1,
    const float* __restrict__ ln_ih1_g, const float* __restrict__ ln_ih1_b,
    const float* __restrict__ ln_hh1_g, const float* __restrict__ ln_hh1_b,
    const float* __restrict__ ln_ho1_g, const float* __restrict__ ln_ho1_b,
    float* __restrict__ out) {
    int r = blockIdx.x;
    int d = r >> 6;       // direction
    int cb = r & 63;      // g-chunk (GEMM role) == b (pointwise role)
    int t = threadIdx.x;
    unsigned target = 0;

    // init layer-0 states
#pragma unroll
    for (int i = 0; i < 2; i++) {
        int j = t + 256 * i;
        g_h[d][cb][j] = 0.f;
        g_c[d][cb][j] = 0.f;
    }
    grid_sync(target);

    // ---- layer 0 scan (both directions in parallel) ----
    for (int st = 0; st < SS; st++) {
        step_gemm(d, cb, w_hh0 + (size_t)d * GG * HH, HH, &g_h[d][0][0], &g_h[d][0][0]);
        grid_sync(target);
        int te = (d == 0) ? st : (SS - 1 - st);
        step_point(d, cb, &g_gih0[d][te][cb][0],
                   ln_hh0_g + d * GG, ln_hh0_b + d * GG,
                   ln_ho0_g + d * HH, ln_ho0_b + d * HH, nullptr);
        grid_sync(target);
    }

    // ---- layer-1 input: g1 = LN(concat(hf,hb) @ W_ih1^T) ----
    step_gemm(d, cb, w_ih1 + (size_t)d * GG * (2 * HH), 2 * HH,
              &g_h[0][0][0], &g_h[1][0][0]);
    grid_sync(target);
    g1_finalize(d, cb, ln_ih1_g + d * GG, ln_ih1_b + d * GG);
    grid_sync(target);

    // ---- layer 1 scan (time-constant input; both dirs identical structure) ----
    for (int st = 0; st < SS; st++) {
        step_gemm(d, cb, w_hh1 + (size_t)d * GG * HH, HH, &g_h[d][0][0], &g_h[d][0][0]);
        grid_sync(target);
        bool last = (st == SS - 1);
        step_point(d, cb, &g_g1[d][cb][0],
                   ln_hh1_g + d * GG, ln_hh1_b + d * GG,
                   ln_ho1_g + d * HH, ln_ho1_b + d * HH,
                   last ? (out + (size_t)cb * 1024 + d * 512) : nullptr);
        if (!last) grid_sync(target);
    }

    // ---- exit protocol: last CTA to leave resets barrier counters ----
    __syncthreads();
    if (t == 0) {
        __threadfence();
        unsigned n = atomicAdd(&g_excnt, 1u) + 1;
        if (n == NCTA) {
            g_barcnt = 0;
            g_excnt = 0;
            __threadfence();
        }
    }
}

// =============================================================================
extern "C" void kernel_launch(void* const* d_in, const int* in_sizes, int n_in,
                              void* d_out, int out_size) {
    const float* x        = (const float*)d_in[0];
    // d_in[1] = text_length (unused by the reference forward)
    const float* w_ih0    = (const float*)d_in[2];
    const float* w_hh0    = (const float*)d_in[3];
    const float* ln_ih0_g = (const float*)d_in[4];
    const float* ln_ih0_b = (const float*)d_in[5];
    const float* ln_hh0_g = (const float*)d_in[6];
    const float* ln_hh0_b = (const float*)d_in[7];
    const float* ln_ho0_g = (const float*)d_in[8];
    const float* ln_ho0_b = (const float*)d_in[9];
    const float* w_ih1    = (const float*)d_in[10];
    const float* w_hh1    = (const float*)d_in[11];
    const float* ln_ih1_g = (const float*)d_in[12];
    const float* ln_ih1_b = (const float*)d_in[13];
    const float* ln_hh1_g = (const float*)d_in[14];
    const float* ln_hh1_b = (const float*)d_in[15];
    const float* ln_ho1_g = (const float*)d_in[16];
    const float* ln_ho1_b = (const float*)d_in[17];
    float* out = (float*)d_out;

    phaseA_gemm<<<2 * SS * 32, 256>>>(x, w_ih0);
    phaseA_ln<<<2 * SS * BB, 256>>>(ln_ih0_g, ln_ih0_b);
    scan_kernel<<<NCTA, 256>>>(w_hh0, ln_hh0_g, ln_hh0_b, ln_ho0_g, ln_ho0_b,
                               w_ih1, w_hh1, ln_ih1_g, ln_ih1_b,
                               ln_hh1_g, ln_hh1_b, ln_ho1_g, ln_ho1_b, out);
}

// round 4
// speedup vs baseline: 2.1342x; 2.1342x over previous
#include <cuda_runtime.h>

#define BB 64
#define SS 48
#define EE 512
#define HH 512
#define GG 2048
#define NCTA 128

// ---------------- persistent device scratch (no allocs allowed) ----------------
__device__ float g_gih0[2][SS][BB][GG];   // LN(x @ W_ih0^T), both dirs  (~50MB)
__device__ float g_u[2][BB][GG];          // per-step h @ W_hh^T (raw)
__device__ float g_h[2][BB][HH];
__device__ unsigned g_barcnt = 0;
__device__ unsigned g_excnt = 0;

__device__ __forceinline__ float sigmoidf_(float x) { return 1.0f / (1.0f + expf(-x)); }

// persistent dynamic smem layout for the scan kernel
struct ScanSmem {
    float hs[2][64][132];    // double-buffered h tile  (k-pad 4 words)
    float ws[2][32][132];    // double-buffered W tile
    float hhg[GG], hhb[GG];  // cached LN_hh params (per dir, per layer)
    float hog[HH], hob[HH];  // cached LN_ho params
    float g1row[GG];         // layer-1 constant input row for this CTA's b
};

// ---------------- grid-wide barrier (all NCTA CTAs co-resident) ----------------
__device__ __forceinline__ void grid_sync(unsigned &target) {
    __syncthreads();
    if (threadIdx.x == 0) {
        __threadfence();                       // release: publish this CTA's stores
        atomicAdd(&g_barcnt, 1u);
        target += NCTA;
        while (*(volatile unsigned*)&g_barcnt < target) { __nanosleep(64); }
        __threadfence();                       // acquire: CCTL.IVALL flushes SM L1D
    }
    __syncthreads();
}

// ---------------- block-wide mean/rstd over (sum, sumsq) contributions ---------
__device__ __forceinline__ void block_stats(float s, float q, float invN,
                                            float &mu, float &rs) {
    __shared__ float redS[8], redQ[8], bc[2];
    int t = threadIdx.x;
    __syncthreads();   // protect shared reuse across calls
#pragma unroll
    for (int o = 16; o > 0; o >>= 1) {
        s += __shfl_xor_sync(0xFFFFFFFFu, s, o);
        q += __shfl_xor_sync(0xFFFFFFFFu, q, o);
    }
    if ((t & 31) == 0) { redS[t >> 5] = s; redQ[t >> 5] = q; }
    __syncthreads();
    if (t == 0) {
        float S = 0.f, Q = 0.f;
#pragma unroll
        for (int i = 0; i < 8; i++) { S += redS[i]; Q += redQ[i]; }
        float m = S * invN;
        bc[0] = m;
        bc[1] = rsqrtf(Q * invN - m * m + 1e-5f);
    }
    __syncthreads();
    mu = bc[0]; rs = bc[1];
}

// ================= Phase A: raw x @ W_ih0^T for all (d, s) =====================
// grid = 2*48*32 = 3072 CTAs; 64b x 64g tile, K = 512, KT = 64.
// Register tile 4b x 4g; both operands staged through shared with coalesced LDG.
__global__ void __launch_bounds__(256, 2) phaseA_gemm(const float* __restrict__ x,
                                                      const float* __restrict__ w_ih0) {
    __shared__ float xs[64][68];
    __shared__ float ws[64][68];
    int r = blockIdx.x;
    int d = r / (SS * 32);
    int rem = r % (SS * 32);
    int s = rem / 32;
    int g0 = (rem % 32) * 64;

    int t = threadIdx.x;
    int tb = t & 15;          // b groups: b = tb + 16*i
    int tg = t >> 4;          // g groups: g = g0 + tg + 16*j

    float acc[4][4];
#pragma unroll
    for (int i = 0; i < 4; i++)
#pragma unroll
        for (int j = 0; j < 4; j++) acc[i][j] = 0.f;

    for (int kt = 0; kt < EE / 64; kt++) {
        int k0 = kt * 64;
#pragma unroll
        for (int i = 0; i < 4; i++) {          // xs: 64x64 = 1024 float4
            int fi = t + 256 * i;
            int b = fi >> 4, kq = fi & 15;
            *(float4*)&xs[b][kq * 4] =
                *(const float4*)(x + ((size_t)b * SS + s) * EE + k0 + kq * 4);
        }
#pragma unroll
        for (int i = 0; i < 4; i++) {          // ws: 64x64 = 1024 float4 (coalesced!)
            int fi = t + 256 * i;
            int gg = fi >> 4, kq = fi & 15;
            *(float4*)&ws[gg][kq * 4] =
                *(const float4*)(w_ih0 + ((size_t)d * GG + g0 + gg) * EE + k0 + kq * 4);
        }
        __syncthreads();
#pragma unroll 4
        for (int k = 0; k < 64; k += 4) {
            float4 wv[4];
#pragma unroll
            for (int j = 0; j < 4; j++) wv[j] = *(float4*)&ws[tg + 16 * j][k];
#pragma unroll
            for (int i = 0; i < 4; i++) {
                float4 hv = *(float4*)&xs[tb + 16 * i][k];
#pragma unroll
                for (int j = 0; j < 4; j++) {
                    acc[i][j] += hv.x * wv[j].x + hv.y * wv[j].y
                               + hv.z * wv[j].z + hv.w * wv[j].w;
                }
            }
        }
        __syncthreads();
    }
#pragma unroll
    for (int i = 0; i < 4; i++) {
        int b = tb + 16 * i;
#pragma unroll
        for (int j = 0; j < 4; j++)
            g_gih0[d][s][b][g0 + tg + 16 * j] = acc[i][j];
    }
}

// ================= Phase A LN (in place, with ln_ih0 params) ===================
__global__ void __launch_bounds__(256) phaseA_ln(const float* __restrict__ gam,
                                                 const float* __restrict__ bet) {
    int r = blockIdx.x;
    int d = r / (SS * BB);
    int rem = r % (SS * BB);
    int s = rem / BB;
    int b = rem % BB;
    float* row = &g_gih0[d][s][b][0];
    int t = threadIdx.x;
    float v[8];
    float sum = 0.f, sq = 0.f;
#pragma unroll
    for (int i = 0; i < 8; i++) {
        v[i] = row[t + 256 * i];
        sum += v[i]; sq += v[i] * v[i];
    }
    float mu, rs;
    block_stats(sum, sq, 1.0f / GG, mu, rs);
    const float* gm = gam + d * GG;
    const float* bt = bet + d * GG;
#pragma unroll
    for (int i = 0; i < 8; i++) {
        int g = t + 256 * i;
        row[g] = (v[i] - mu) * rs * gm[g] + bt[g];
    }
}

// ================= scan GEMM: 64b x 32g tile, K in {512,1024} ==================
// Register tile 4b x 2g; W staged via shared (coalesced); double-buffered.
__device__ void step_gemm(ScanSmem* sm, int d, int chunk, const float* __restrict__ Wd,
                          int K, const float* __restrict__ src0,
                          const float* __restrict__ src1) {
    int t = threadIdx.x;
    int tb = t & 15;              // b = tb + 16*i
    int tg = t >> 4;              // g(local) = 2*tg, 2*tg+1
    int nt = K >> 7;
    const float* Wbase = Wd + (size_t)chunk * 32 * K;

    // prologue: load tile 0
#pragma unroll
    for (int i = 0; i < 8; i++) {
        int fi = t + 256 * i;
        int b = fi >> 5, kq = fi & 31;
        *(float4*)&sm->hs[0][b][kq * 4] = *(const float4*)(src0 + (size_t)b * HH + kq * 4);
    }
#pragma unroll
    for (int i = 0; i < 4; i++) {
        int fi = t + 256 * i;
        int g = fi >> 5, kq = fi & 31;
        *(float4*)&sm->ws[0][g][kq * 4] = *(const float4*)(Wbase + (size_t)g * K + kq * 4);
    }
    __syncthreads();

    float acc[4][2];
#pragma unroll
    for (int i = 0; i < 4; i++) { acc[i][0] = 0.f; acc[i][1] = 0.f; }

    for (int kt = 0; kt < nt; kt++) {
        int cur = kt & 1;
        if (kt + 1 < nt) {                      // prefetch next tile into other buffer
            int k0 = (kt + 1) << 7;
            const float* src = (k0 < HH) ? (src0 + k0) : (src1 + (k0 - HH));
            int nxt = cur ^ 1;
#pragma unroll
            for (int i = 0; i < 8; i++) {
                int fi = t + 256 * i;
                int b = fi >> 5, kq = fi & 31;
                *(float4*)&sm->hs[nxt][b][kq * 4] =
                    *(const float4*)(src + (size_t)b * HH + kq * 4);
            }
#pragma unroll
            for (int i = 0; i < 4; i++) {
                int fi = t + 256 * i;
                int g = fi >> 5, kq = fi & 31;
                *(float4*)&sm->ws[nxt][g][kq * 4] =
                    *(const float4*)(Wbase + (size_t)g * K + k0 + kq * 4);
            }
        }
#pragma unroll 4
        for (int k = 0; k < 128; k += 4) {
            float4 wv0 = *(float4*)&sm->ws[cur][2 * tg][k];
            float4 wv1 = *(float4*)&sm->ws[cur][2 * tg + 1][k];
#pragma unroll
            for (int i = 0; i < 4; i++) {
                float4 hv = *(float4*)&sm->hs[cur][tb + 16 * i][k];
                acc[i][0] += hv.x * wv0.x + hv.y * wv0.y + hv.z * wv0.z + hv.w * wv0.w;
                acc[i][1] += hv.x * wv1.x + hv.y * wv1.y + hv.z * wv1.z + hv.w * wv1.w;
            }
        }
        __syncthreads();
    }
#pragma unroll
    for (int i = 0; i < 4; i++) {
        int b = tb + 16 * i;
        *(float2*)&g_u[d][b][chunk * 32 + 2 * tg] = make_float2(acc[i][0], acc[i][1]);
    }
}

// ================= pointwise: CTA owns row (d, b); c kept in registers =========
__device__ void step_point(ScanSmem* sm, int d, int b, const float* __restrict__ gih,
                           float (&c)[2], float* __restrict__ outrow) {
    int t = threadIdx.x;
    const float* urow = &g_u[d][b][0];
    float uv[8];
    float s = 0.f, q = 0.f;
#pragma unroll
    for (int i = 0; i < 8; i++) {
        uv[i] = urow[t + 256 * i];
        s += uv[i]; q += uv[i] * uv[i];
    }
    float mu, rs;
    block_stats(s, q, 1.0f / GG, mu, rs);

    float cn[2], og[2];
    float cs = 0.f, cq = 0.f;
#pragma unroll
    for (int i = 0; i < 2; i++) {
        int j = t + 256 * i;
        float vi = gih[j]        + (uv[0 + i] - mu) * rs * sm->hhg[j]        + sm->hhb[j];
        float vf = gih[512 + j]  + (uv[2 + i] - mu) * rs * sm->hhg[512 + j]  + sm->hhb[512 + j];
        float vo = gih[1024 + j] + (uv[4 + i] - mu) * rs * sm->hhg[1024 + j] + sm->hhb[1024 + j];
        float vg = gih[1536 + j] + (uv[6 + i] - mu) * rs * sm->hhg[1536 + j] + sm->hhb[1536 + j];
        float ig = sigmoidf_(vi);
        float fg = sigmoidf_(vf);
        og[i] = sigmoidf_(vo);
        float gv = tanhf(vg);
        float cc = fg * c[i] + ig * gv;
        cn[i] = cc;
        cs += cc; cq += cc * cc;
    }
    float muc, rsc;
    block_stats(cs, cq, 1.0f / HH, muc, rsc);
#pragma unroll
    for (int i = 0; i < 2; i++) {
        int j = t + 256 * i;
        float hval = og[i] * tanhf((cn[i] - muc) * rsc * sm->hog[j] + sm->hob[j]);
        c[i] = cn[i];
        g_h[d][b][j] = hval;
        if (outrow) outrow[j] = hval;
    }
}

// layer-1 input LN into persistent smem; zero h for layer 1
__device__ void g1_finalize(ScanSmem* sm, int d, int b, const float* __restrict__ ihg,
                            const float* __restrict__ ihb) {
    int t = threadIdx.x;
    const float* urow = &g_u[d][b][0];
    float uv[8];
    float s = 0.f, q = 0.f;
#pragma unroll
    for (int i = 0; i < 8; i++) {
        uv[i] = urow[t + 256 * i];
        s += uv[i]; q += uv[i] * uv[i];
    }
    float mu, rs;
    block_stats(s, q, 1.0f / GG, mu, rs);
#pragma unroll
    for (int i = 0; i < 8; i++) {
        int g = t + 256 * i;
        sm->g1row[g] = (uv[i] - mu) * rs * ihg[g] + ihb[g];
    }
#pragma unroll
    for (int i = 0; i < 2; i++) g_h[d][b][t + 256 * i] = 0.f;
}

__device__ void load_params(ScanSmem* sm, const float* __restrict__ hhg,
                            const float* __restrict__ hhb, const float* __restrict__ hog,
                            const float* __restrict__ hob) {
    int t = threadIdx.x;
#pragma unroll
    for (int i = 0; i < 8; i++) {
        int j = t + 256 * i;
        sm->hhg[j] = hhg[j];
        sm->hhb[j] = hhb[j];
    }
#pragma unroll
    for (int i = 0; i < 2; i++) {
        int j = t + 256 * i;
        sm->hog[j] = hog[j];
        sm->hob[j] = hob[j];
    }
}

// ================= persistent recurrent kernel ================================
__global__ void __launch_bounds__(256, 1) scan_kernel(
    const float* __restrict__ w_hh0,
    const float* __restrict__ ln_hh0_g, const float* __restrict__ ln_hh0_b,
    const float* __restrict__ ln_ho0_g, const float* __restrict__ ln_ho0_b,
    const float* __restrict__ w_ih1, const float* __restrict__ w_hh1,
    const float* __restrict__ ln_ih1_g, const float* __restrict__ ln_ih1_b,
    const float* __restrict__ ln_hh1_g, const float* __restrict__ ln_hh1_b,
    const float* __restrict__ ln_ho1_g, const float* __restrict__ ln_ho1_b,
    float* __restrict__ out) {
    extern __shared__ float smbuf[];
    ScanSmem* sm = (ScanSmem*)smbuf;

    int r = blockIdx.x;
    int d = r >> 6;       // direction
    int cb = r & 63;      // g-chunk (GEMM role) == b (pointwise role)
    int t = threadIdx.x;
    unsigned target = 0;
    float c[2] = {0.f, 0.f};

    load_params(sm, ln_hh0_g + d * GG, ln_hh0_b + d * GG,
                ln_ho0_g + d * HH, ln_ho0_b + d * HH);
#pragma unroll
    for (int i = 0; i < 2; i++) g_h[d][cb][t + 256 * i] = 0.f;
    grid_sync(target);

    // ---- layer 0 scan (both directions in parallel across CTAs) ----
    const float* h0 = &g_h[d][0][0];
    for (int st = 0; st < SS; st++) {
        step_gemm(sm, d, cb, w_hh0 + (size_t)d * GG * HH, HH, h0, h0);
        grid_sync(target);
        int te = (d == 0) ? st : (SS - 1 - st);
        step_point(sm, d, cb, &g_gih0[d][te][cb][0], c, nullptr);
        grid_sync(target);
    }

    // ---- layer-1 input: g1 = LN(concat(hf,hb) @ W_ih1^T), cached in smem ----
    step_gemm(sm, d, cb, w_ih1 + (size_t)d * GG * (2 * HH), 2 * HH,
              &g_h[0][0][0], &g_h[1][0][0]);
    grid_sync(target);
    g1_finalize(sm, d, cb, ln_ih1_g + d * GG, ln_ih1_b + d * GG);
    c[0] = 0.f; c[1] = 0.f;
    __syncthreads();
    load_params(sm, ln_hh1_g + d * GG, ln_hh1_b + d * GG,
                ln_ho1_g + d * HH, ln_ho1_b + d * HH);
    grid_sync(target);

    // ---- layer 1 scan (time-constant input) ----
    for (int st = 0; st < SS; st++) {
        step_gemm(sm, d, cb, w_hh1 + (size_t)d * GG * HH, HH, h0, h0);
        grid_sync(target);
        bool last = (st == SS - 1);
        step_point(sm, d, cb, sm->g1row, c,
                   last ? (out + (size_t)cb * 1024 + d * 512) : nullptr);
        if (!last) grid_sync(target);
    }

    // ---- exit protocol: last CTA to leave resets barrier counters ----
    __syncthreads();
    if (t == 0) {
        __threadfence();
        unsigned n = atomicAdd(&g_excnt, 1u) + 1;
        if (n == NCTA) {
            g_barcnt = 0;
            g_excnt = 0;
            __threadfence();
        }
    }
}

// =============================================================================
extern "C" void kernel_launch(void* const* d_in, const int* in_sizes, int n_in,
                              void* d_out, int out_size) {
    const float* x        = (const float*)d_in[0];
    // d_in[1] = text_length (unused by the reference forward)
    const float* w_ih0    = (const float*)d_in[2];
    const float* w_hh0    = (const float*)d_in[3];
    const float* ln_ih0_g = (const float*)d_in[4];
    const float* ln_ih0_b = (const float*)d_in[5];
    const float* ln_hh0_g = (const float*)d_in[6];
    const float* ln_hh0_b = (const float*)d_in[7];
    const float* ln_ho0_g = (const float*)d_in[8];
    const float* ln_ho0_b = (const float*)d_in[9];
    const float* w_ih1    = (const float*)d_in[10];
    const float* w_hh1    = (const float*)d_in[11];
    const float* ln_ih1_g = (const float*)d_in[12];
    const float* ln_ih1_b = (const float*)d_in[13];
    const float* ln_hh1_g = (const float*)d_in[14];
    const float* ln_hh1_b = (const float*)d_in[15];
    const float* ln_ho1_g = (const float*)d_in[16];
    const float* ln_ho1_b = (const float*)d_in[17];
    float* out = (float*)d_out;

    static int smem_set = 0;
    if (!smem_set) {
        cudaFuncSetAttribute(scan_kernel, cudaFuncAttributeMaxDynamicSharedMemorySize,
                             (int)sizeof(ScanSmem));
        smem_set = 1;
    }

    phaseA_gemm<<<2 * SS * 32, 256>>>(x, w_ih0);
    phaseA_ln<<<2 * SS * BB, 256>>>(ln_ih0_g, ln_ih0_b);
    scan_kernel<<<NCTA, 256, sizeof(ScanSmem)>>>(
        w_hh0, ln_hh0_g, ln_hh0_b, ln_ho0_g, ln_ho0_b,
        w_ih1, w_hh1, ln_ih1_g, ln_ih1_b,
        ln_hh1_g, ln_hh1_b, ln_ho1_g, ln_ho1_b, out);
}